// round 14
// baseline (speedup 1.0000x reference)
#include <cuda_runtime.h>
#include <cuda_fp16.h>
#include <cstdint>

#define N_NODES 50000
#define N_EDGES 1600000
#define N_GRAPHS 2048
#define D 133
#define DPH 144          // fp16 padded row (halves) = 288B (9 sectors), pair-permuted
#define PW 144           // pool row width (floats), stored-column space
#define WKH 144          // W smem k-stride in halves (72 words; 72%32=8 -> LDS.64 conflict-free)
#define EPSV 1e-5f
#define SCAN_B 1024
#define SCAN_NB ((N_NODES + SCAN_B - 1) / SCAN_B)   // 49

// Column-word permutation (within each 8-word group):
//   stored[g*8 + 2*kc]   = orig[g*8 + kc]
//   stored[g*8 + 2*kc+1] = orig[g*8 + kc + 4]
__host__ __device__ __forceinline__ int sw2orig(int s) {
    int r = s & 7;
    return (s & ~7) + (r >> 1) + ((r & 1) << 2);
}
__host__ __device__ __forceinline__ int orig2sw(int o) {
    int r = o & 7;
    return (o & ~7) + ((r < 4) ? (2 * r) : (2 * (r - 4) + 1));
}

// -------- scratch (static device globals; no runtime allocation) --------
__device__ __align__(16) __half g_A16[(size_t)N_NODES * DPH];  // gemm out (messages), permuted cols
__device__ __align__(16) __half g_X16[(size_t)N_NODES * DPH];  // gemm in, permuted cols
__device__ __align__(16) float  g_P[(size_t)N_GRAPHS * PW];    // pool accumulator (stored-col space)
__device__ __align__(16) __half g_W2th[136 * WKH];             // W2 fp16 [n][k], k-words permuted
__device__ float g_dinv[N_NODES];
__device__ int   g_cnt[N_NODES];
__device__ int   g_off[N_NODES + 1];
__device__ int   g_cursor[N_NODES];
__device__ int   g_csr[N_EDGES];
__device__ int   g_bsum[SCAN_NB];
__device__ int   g_cntg[N_GRAPHS];
__device__ float g_post1[3 * PW];    // bias | s | t  in stored-col order, zero-padded
__device__ float g_post2[3 * PW];

// ------------------------------------------------------------------
__global__ void zero_fused_kernel() {
    int i = blockIdx.x * blockDim.x + threadIdx.x;
    if (i < N_GRAPHS * PW) g_P[i] = 0.0f;
    if (i < N_NODES)       g_cnt[i] = 0;
}

__global__ void count_deg_kernel(const int* __restrict__ ei) {
    int e = blockIdx.x * blockDim.x + threadIdx.x;
    if (e < N_EDGES) atomicAdd(&g_cnt[__ldg(&ei[N_EDGES + e])], 1);
}

__device__ __forceinline__ uint32_t pack2h(float x, float y) {
    __half2 h = __floats2half2_rn(x, y);
    return *(uint32_t*)&h;
}

// fused: X (fp32 [N,133]) -> g_X16 (fp16 [N,144], permuted, pads 0), and dinv.
// thread: row = idx/36, m = idx%36 -> stored words (2m, 2m+1) = orig words (oA, oA+4).
__global__ void prep_x_dinv_kernel(const float* __restrict__ X) {
    int idx = blockIdx.x * blockDim.x + threadIdx.x;
    if (idx < N_NODES) g_dinv[idx] = rsqrtf((float)(g_cnt[idx] + 1));
    if (idx >= N_NODES * 36) return;
    int row = idx / 36;
    int m   = idx - row * 36;
    int oA  = sw2orig(2 * m);        // even stored word
    int oB  = oA + 4;                // odd stored word
    const float* Xr = X + (size_t)row * D;
    int cA = 2 * oA, cB = 2 * oB;
    float fA0 = (cA     < D) ? __ldg(Xr + cA)     : 0.0f;
    float fA1 = (cA + 1 < D) ? __ldg(Xr + cA + 1) : 0.0f;
    float fB0 = (cB     < D) ? __ldg(Xr + cB)     : 0.0f;
    float fB1 = (cB + 1 < D) ? __ldg(Xr + cB + 1) : 0.0f;
    ((uint2*)(g_X16 + (size_t)row * DPH))[m] = make_uint2(pack2h(fA0, fA1), pack2h(fB0, fB1));
}

// ---- 3-kernel exclusive scan of g_cnt -> g_off ----
__global__ void scan1_kernel() {
    __shared__ int sh[SCAN_B];
    int t = threadIdx.x;
    int i = blockIdx.x * SCAN_B + t;
    int v = (i < N_NODES) ? g_cnt[i] : 0;
    sh[t] = v;
    __syncthreads();
#pragma unroll
    for (int d = 1; d < SCAN_B; d <<= 1) {
        int x = (t >= d) ? sh[t - d] : 0;
        __syncthreads();
        sh[t] += x;
        __syncthreads();
    }
    if (i < N_NODES) g_off[i] = sh[t] - v;
    if (t == SCAN_B - 1) g_bsum[blockIdx.x] = sh[t];
}

__global__ void scan2_kernel() {
    if (threadIdx.x == 0) {
        int acc = 0;
        for (int b = 0; b < SCAN_NB; b++) {
            int v = g_bsum[b];
            g_bsum[b] = acc;
            acc += v;
        }
    }
}

__global__ void scan3_kernel() {
    int i = blockIdx.x * blockDim.x + threadIdx.x;
    if (i < N_NODES) {
        int o = g_off[i] + g_bsum[i / SCAN_B];
        g_off[i] = o;
        g_cursor[i] = o;
    }
    if (i == 0) g_off[N_NODES] = N_EDGES;
}

__global__ void fill_csr_kernel(const int* __restrict__ ei) {
    int e = blockIdx.x * blockDim.x + threadIdx.x;
    if (e < N_EDGES) {
        int r = __ldg(&ei[e]);
        int c = __ldg(&ei[N_EDGES + e]);
        int pos = atomicAdd(&g_cursor[c], 1);
        g_csr[pos] = r;
    }
}

// ---- fused BN constants in STORED column order: bias | s | t (width PW) ----
__global__ void prep_post_kernel(const float* __restrict__ bias, const float* __restrict__ gam,
                                 const float* __restrict__ beta, const float* __restrict__ rm,
                                 const float* __restrict__ rv, float* __restrict__ dst) {
    int sc = threadIdx.x;
    if (sc >= PW) return;
    int o = sw2orig(sc >> 1);
    int c = 2 * o + (sc & 1);        // original column
    float bb = 0.0f, ss = 0.0f, tt = 0.0f;
    if (c < D) {
        bb = bias[c];
        float s = gam[c] * rsqrtf(rv[c] + EPSV);
        ss = s;
        tt = beta[c] - rm[c] * s;
    }
    dst[sc] = bb; dst[PW + sc] = ss; dst[2 * PW + sc] = tt;
}

// W2 -> fp16 [n][WKH], k-words permuted, zero-padded
__global__ void w_cvt_h_kernel(const float* __restrict__ W, __half* __restrict__ Wt) {
    int i = blockIdx.x * blockDim.x + threadIdx.x;
    if (i >= 136 * WKH) return;
    int n  = i / WKH;
    int sc = i - n * WKH;
    int o  = sw2orig(sc >> 1);
    int k  = 2 * o + (sc & 1);
    float v = (k < D && n < D) ? __ldg(&W[k * D + n]) : 0.0f;
    Wt[i] = __float2half(v);
}

__device__ __forceinline__ void mma_f16(float* d,
                                        uint32_t a0, uint32_t a1, uint32_t a2, uint32_t a3,
                                        uint32_t b0, uint32_t b1) {
    asm volatile("mma.sync.aligned.m16n8k16.row.col.f32.f16.f16.f32 "
                 "{%0,%1,%2,%3}, {%4,%5,%6,%7}, {%8,%9}, {%0,%1,%2,%3};"
                 : "+f"(d[0]), "+f"(d[1]), "+f"(d[2]), "+f"(d[3])
                 : "r"(a0), "r"(a1), "r"(a2), "r"(a3), "r"(b0), "r"(b1));
}

// Tensor-core GEMM (fp16 m16n8k16): g_A16[row] = fp16( dinv[row] * (Xh @ W) ).
// All fp16 buffers pair-permuted -> A: 2x LDG.64/k-step, B: 9x LDS.64/k-step.
template <bool CVT>
__global__ __launch_bounds__(256, 4)
void gemm_tc_kernel(const __half* __restrict__ Xh,
                    const float* __restrict__ Wf, const __half* __restrict__ Wth) {
    extern __shared__ __half wsh[];          // [136 n][WKH k] fp16, k-words permuted

    int tid  = threadIdx.x;
    int w    = tid >> 5;
    int lane = tid & 31;

    if (CVT) {
        // layer 1: f32 W [k][n] -> wsh[n][permuted k], one word per iter
        for (int idx = tid; idx < 136 * 72; idx += 256) {
            int n = idx / 72;
            int s = idx - n * 72;
            int o = sw2orig(s);
            int k0 = 2 * o, k1 = 2 * o + 1;
            float f0 = (k0 < D && n < D) ? __ldg(&Wf[k0 * D + n]) : 0.0f;
            float f1 = (k1 < D && n < D) ? __ldg(&Wf[k1 * D + n]) : 0.0f;
            *(uint32_t*)&wsh[n * WKH + 2 * s] = pack2h(f0, f1);
        }
    } else {
        const uint4* src = (const uint4*)Wth;
        uint4* dst = (uint4*)wsh;
#pragma unroll 4
        for (int i = tid; i < (136 * WKH) / 8; i += 256) dst[i] = __ldg(&src[i]);
    }
    __syncthreads();

    const int r0 = lane >> 2;        // A row group / B n
    const int kc = lane & 3;         // A/B k quad
    const int colhalf = w & 1;
    const int ntBase = colhalf * 9;
    const int ntCnt  = 9 - colhalf;  // 9 or 8 tiles

    int rowbase = blockIdx.x * 64 + (w >> 1) * 16;
    int row0 = rowbase + r0;
    int row1 = row0 + 8;
    bool v0 = row0 < N_NODES;
    bool v1 = row1 < N_NODES;
    const uint2* x0q = (const uint2*)(Xh + (size_t)(v0 ? row0 : 0) * DPH);
    const uint2* x1q = (const uint2*)(Xh + (size_t)(v1 ? row1 : 0) * DPH);

    // B base: uint2 index = n*36 + ks*4 + kc, n = ntBase*8 + j*8 + r0
    const uint2* wb2 = (const uint2*)wsh + (ntBase * 8 + r0) * 36 + kc;

    float acc[9][4];
#pragma unroll
    for (int j = 0; j < 9; j++)
#pragma unroll
        for (int q = 0; q < 4; q++) acc[j][q] = 0.0f;

    uint2 A0 = __ldg(x0q + kc);      // ks=0
    uint2 A1 = __ldg(x1q + kc);

#pragma unroll
    for (int ks = 0; ks < 9; ks++) {
        uint2 nA0 = make_uint2(0, 0), nA1 = make_uint2(0, 0);
        if (ks < 8) {
            nA0 = __ldg(x0q + (ks + 1) * 4 + kc);
            nA1 = __ldg(x1q + (ks + 1) * 4 + kc);
        }
#pragma unroll
        for (int j = 0; j < 9; j++) {
            if (j < ntCnt) {
                uint2 b = wb2[j * 288 + ks * 4];   // 288 = 8 rows * 36 uint2
                mma_f16(acc[j], A0.x, A1.x, A0.y, A1.y, b.x, b.y);
            }
        }
        A0 = nA0; A1 = nA1;
    }

    // epilogue: D-frag word o = 4j+kc -> stored word orig2sw(o); dinv scale -> fp16
    float dv0 = v0 ? g_dinv[row0] : 0.0f;
    float dv1 = v1 ? g_dinv[row1] : 0.0f;
#pragma unroll
    for (int j = 0; j < 9; j++) {
        if (j < ntCnt) {
            int o = 4 * (ntBase + j) + kc;
            int s = orig2sw(o);
            if (v0)
                *(__half2*)(g_A16 + (size_t)row0 * DPH + 2 * s) =
                    __floats2half2_rn(dv0 * acc[j][0], dv0 * acc[j][1]);
            if (v1)
                *(__half2*)(g_A16 + (size_t)row1 * DPH + 2 * s) =
                    __floats2half2_rn(dv1 * acc[j][2], dv1 * acc[j][3]);
        }
    }
}

// ------------------------------------------------------------------
// Warp-per-node CSR gather in stored-column space (permutation-invariant sum).
// lane l: uint2 idx l (stored cols 4l..4l+3); lanes 0-3 also idx 32+l (cols 128+4l..).
// POOL=0: write fp16 permuted row to g_X16.  POOL=1: red.v4 into g_P (stored cols).
template <int POOL>
__global__ __launch_bounds__(256)
void gather_post_kernel(const __half* __restrict__ A,
                        const float* __restrict__ post,
                        const int* __restrict__ batch) {
    int gw = (blockIdx.x * blockDim.x + threadIdx.x) >> 5;
    if (gw >= N_NODES) return;
    int lane = threadIdx.x & 31;
    int n = gw;

    int lo = __ldg(&g_off[n]);
    int hi = __ldg(&g_off[n + 1]);
    bool tl = lane < 4;

    float a0 = 0.f, a1 = 0.f, a2 = 0.f, a3 = 0.f;
    float t0 = 0.f, t1 = 0.f, t2 = 0.f, t3 = 0.f;

#define ACCUM(SJ) do {                                                        \
        const uint2* R = (const uint2*)(A + (size_t)(SJ) * DPH);              \
        uint2 m = __ldg(R + lane);                                            \
        float2 f0 = __half22float2(*(const __half2*)&m.x);                    \
        float2 f1 = __half22float2(*(const __half2*)&m.y);                    \
        a0 += f0.x; a1 += f0.y; a2 += f1.x; a3 += f1.y;                       \
        if (tl) {                                                             \
            uint2 mt = __ldg(R + 32 + lane);                                  \
            float2 g0 = __half22float2(*(const __half2*)&mt.x);               \
            float2 g1 = __half22float2(*(const __half2*)&mt.y);               \
            t0 += g0.x; t1 += g0.y; t2 += g1.x; t3 += g1.y;                   \
        }                                                                     \
    } while (0)

    ACCUM(n);   // self-loop term

    int e = lo;
    for (; e + 32 <= hi; e += 32) {
        int src = __ldg(&g_csr[e + lane]);
#pragma unroll 4
        for (int j = 0; j < 32; j++) {
            int sj = __shfl_sync(0xffffffffu, src, j);
            ACCUM(sj);
        }
    }
    for (; e < hi; e++) {
        int sj = __ldg(&g_csr[e]);
        ACCUM(sj);
    }
#undef ACCUM

    float dv = __ldg(&g_dinv[n]);
    const float* bb = post;
    const float* ss = post + PW;
    const float* tt = post + 2 * PW;

    int c0 = 4 * lane;               // stored cols
    float4 o;
    o.x = fmaf(fmaxf(fmaf(dv, a0, __ldg(&bb[c0 + 0])), 0.f), __ldg(&ss[c0 + 0]), __ldg(&tt[c0 + 0]));
    o.y = fmaf(fmaxf(fmaf(dv, a1, __ldg(&bb[c0 + 1])), 0.f), __ldg(&ss[c0 + 1]), __ldg(&tt[c0 + 1]));
    o.z = fmaf(fmaxf(fmaf(dv, a2, __ldg(&bb[c0 + 2])), 0.f), __ldg(&ss[c0 + 2]), __ldg(&tt[c0 + 2]));
    o.w = fmaf(fmaxf(fmaf(dv, a3, __ldg(&bb[c0 + 3])), 0.f), __ldg(&ss[c0 + 3]), __ldg(&tt[c0 + 3]));
    float4 ot = make_float4(0.f, 0.f, 0.f, 0.f);
    if (tl) {
        int ct = 128 + 4 * lane;     // stored cols 128..143
        ot.x = fmaf(fmaxf(fmaf(dv, t0, __ldg(&bb[ct + 0])), 0.f), __ldg(&ss[ct + 0]), __ldg(&tt[ct + 0]));
        ot.y = fmaf(fmaxf(fmaf(dv, t1, __ldg(&bb[ct + 1])), 0.f), __ldg(&ss[ct + 1]), __ldg(&tt[ct + 1]));
        ot.z = fmaf(fmaxf(fmaf(dv, t2, __ldg(&bb[ct + 2])), 0.f), __ldg(&ss[ct + 2]), __ldg(&tt[ct + 2]));
        ot.w = fmaf(fmaxf(fmaf(dv, t3, __ldg(&bb[ct + 3])), 0.f), __ldg(&ss[ct + 3]), __ldg(&tt[ct + 3]));
    }

    if (POOL == 0) {
        // permuted fp16 row for the next GEMM; stored-pad cols get 0 via zero BN consts
        uint2* Cr = (uint2*)(g_X16 + (size_t)n * DPH);
        Cr[lane] = make_uint2(pack2h(o.x, o.y), pack2h(o.z, o.w));
        if (tl) Cr[32 + lane] = make_uint2(pack2h(ot.x, ot.y), pack2h(ot.z, ot.w));
    } else {
        int g = __ldg(&batch[n]);
        float* dst = g_P + (size_t)g * PW + c0;
        unsigned long long p0 = (unsigned long long)__cvta_generic_to_global(dst);
        asm volatile("red.global.add.v4.f32 [%0], {%1,%2,%3,%4};"
                     :: "l"(p0), "f"(o.x), "f"(o.y), "f"(o.z), "f"(o.w) : "memory");
        if (tl) {
            float* dt = g_P + (size_t)g * PW + 128 + 4 * lane;
            unsigned long long p1 = (unsigned long long)__cvta_generic_to_global(dt);
            asm volatile("red.global.add.v4.f32 [%0], {%1,%2,%3,%4};"
                         :: "l"(p1), "f"(ot.x), "f"(ot.y), "f"(ot.z), "f"(ot.w) : "memory");
        }
    }
}

// ------------------------------------------------------------------
__device__ __forceinline__ int lbound(const int* b, int n, int v) {
    int lo = 0, hi = n;
    while (lo < hi) { int m = (lo + hi) >> 1; if (b[m] < v) lo = m + 1; else hi = m; }
    return lo;
}

__global__ void cntg_kernel(const int* __restrict__ batch) {
    int g = blockIdx.x * blockDim.x + threadIdx.x;
    if (g < N_GRAPHS)
        g_cntg[g] = lbound(batch, N_NODES, g + 1) - lbound(batch, N_NODES, g);
}

// un-permute: out[g, c] = g_P[g, stored(c)] / cnt
__global__ void divide_kernel(float* __restrict__ out) {
    int idx = blockIdx.x * blockDim.x + threadIdx.x;
    if (idx >= N_GRAPHS * D) return;
    int g = idx / D;
    int c = idx - g * D;
    int s = orig2sw(c >> 1);
    float cnt = (float)g_cntg[g];
    out[idx] = g_P[(size_t)g * PW + 2 * s + (c & 1)] / fmaxf(cnt, 1.0f);
}

// ------------------------------------------------------------------
extern "C" void kernel_launch(void* const* d_in, const int* in_sizes, int n_in,
                              void* d_out, int out_size) {
    const float* x     = (const float*)d_in[0];
    const int*   ei    = (const int*)d_in[1];
    const int*   batch = (const int*)d_in[2];
    const float* W1  = (const float*)d_in[3];
    const float* b1  = (const float*)d_in[4];
    const float* W2  = (const float*)d_in[5];
    const float* b2  = (const float*)d_in[6];
    const float* g1  = (const float*)d_in[7];
    const float* be1 = (const float*)d_in[8];
    const float* rm1 = (const float*)d_in[9];
    const float* rv1 = (const float*)d_in[10];
    const float* g2  = (const float*)d_in[11];
    const float* be2 = (const float*)d_in[12];
    const float* rm2 = (const float*)d_in[13];
    const float* rv2 = (const float*)d_in[14];
    float* out = (float*)d_out;

    __half *pA, *pX, *pW2th;
    float *pP1, *pP2;
    cudaGetSymbolAddress((void**)&pA, g_A16);
    cudaGetSymbolAddress((void**)&pX, g_X16);
    cudaGetSymbolAddress((void**)&pP1, g_post1);
    cudaGetSymbolAddress((void**)&pP2, g_post2);
    cudaGetSymbolAddress((void**)&pW2th, g_W2th);

    // side stream + fork/join events, created once (no device allocation)
    static cudaStream_t s_side = nullptr;
    static cudaEvent_t ev_fork = nullptr, ev_join = nullptr;
    if (!s_side) {
        cudaStreamCreateWithFlags(&s_side, cudaStreamNonBlocking);
        cudaEventCreateWithFlags(&ev_fork, cudaEventDisableTiming);
        cudaEventCreateWithFlags(&ev_join, cudaEventDisableTiming);
    }

    const int smem = 136 * WKH * (int)sizeof(__half);           // 39.2 KB
    cudaFuncSetAttribute((const void*)gemm_tc_kernel<true>,
                         cudaFuncAttributeMaxDynamicSharedMemorySize, smem);
    cudaFuncSetAttribute((const void*)gemm_tc_kernel<false>,
                         cudaFuncAttributeMaxDynamicSharedMemorySize, smem);

    const int TB = 256;
    const int gemm_blocks   = (N_NODES + 63) / 64;                // 782
    const int gather_blocks = (N_NODES * 32 + TB - 1) / TB;       // warp per node

    // ---- main: zero(1), count(2), prep_x+dinv(3), gemm1(4) -> ncu sees gemm1 ----
    zero_fused_kernel<<<(N_GRAPHS * PW + TB - 1) / TB, TB>>>();
    count_deg_kernel<<<(N_EDGES + TB - 1) / TB, TB>>>(ei);
    cudaEventRecord(ev_fork, 0);
    prep_x_dinv_kernel<<<(N_NODES * 36 + TB - 1) / TB, TB>>>(x);
    gemm_tc_kernel<true><<<gemm_blocks, TB, smem>>>(pX, W1, nullptr);

    // ---- side: CSR build + misc, overlapped with gemm1 ----
    cudaStreamWaitEvent(s_side, ev_fork, 0);
    scan1_kernel<<<SCAN_NB, SCAN_B, 0, s_side>>>();
    scan2_kernel<<<1, 32, 0, s_side>>>();
    scan3_kernel<<<SCAN_NB, SCAN_B, 0, s_side>>>();
    fill_csr_kernel<<<(N_EDGES + TB - 1) / TB, TB, 0, s_side>>>(ei);
    w_cvt_h_kernel<<<(136 * WKH + TB - 1) / TB, TB, 0, s_side>>>(W2, pW2th);
    prep_post_kernel<<<1, PW, 0, s_side>>>(b1, g1, be1, rm1, rv1, pP1);
    prep_post_kernel<<<1, PW, 0, s_side>>>(b2, g2, be2, rm2, rv2, pP2);
    cntg_kernel<<<(N_GRAPHS + TB - 1) / TB, TB, 0, s_side>>>(batch);
    cudaEventRecord(ev_join, s_side);

    // ---- join, then the serial tail ----
    cudaStreamWaitEvent(0, ev_join, 0);
    gather_post_kernel<0><<<gather_blocks, TB>>>(pA, pP1, batch);   // -> g_X16
    gemm_tc_kernel<false><<<gemm_blocks, TB, smem>>>(pX, nullptr, pW2th);
    gather_post_kernel<1><<<gather_blocks, TB>>>(pA, pP2, batch);   // -> g_P
    divide_kernel<<<(N_GRAPHS * D + TB - 1) / TB, TB>>>(out);
}